// round 1
// baseline (speedup 1.0000x reference)
#include <cuda_runtime.h>
#include <cuda_bf16.h>
#include <math.h>

// ---------------- Problem constants ----------------
#define T_SEQ   2048
#define HID     5120
#define NH      16
#define D_NOPE  128
#define D_ROPE  64
#define D_V     128
#define Q_LORA  1536
#define KV_LORA 512
#define QK_HD   (D_NOPE + D_ROPE)   // 192
#define KVA_N   (KV_LORA + D_ROPE)  // 576
#define QB_N    (NH * QK_HD)        // 3072
#define KVB_N   (NH * (D_NOPE + D_V)) // 4096
#define O_K     (NH * D_V)          // 2048

static const float SCALE = 0.07216878364870322f; // 192^-0.5
#define EPS_RMS 1e-6f

// ---------------- Scratch (static device globals; no allocation) ----------------
__device__ float g_qa   [T_SEQ * Q_LORA];          // hs @ w_qa
__device__ float g_qc   [T_SEQ * Q_LORA];          // rmsnorm(g_qa)
__device__ float g_q    [T_SEQ * QB_N];            // g_qc @ w_qb
__device__ float g_kv   [T_SEQ * KVA_N];           // hs @ w_kva
__device__ float g_kvc  [T_SEQ * KV_LORA];         // rmsnorm(g_kv[:, :512])
__device__ float g_kvup [T_SEQ * KVB_N];           // g_kvc @ w_kvb
__device__ float g_qfull[(long)NH * T_SEQ * QK_HD];// [h][t][192]
__device__ float g_kfull[(long)NH * T_SEQ * QK_HD];// [h][t][192]
__device__ float g_v    [(long)NH * T_SEQ * D_V];  // [h][t][128]
__device__ float g_scores[(long)NH * T_SEQ * T_SEQ]; // [h][t][s], 268MB
__device__ float g_attn [T_SEQ * O_K];             // [t][h*128+d]

// ---------------- Generic tiled SGEMM ----------------
// C[M,N] = alpha * A @ B    (TRANSB==0 : B is K x N row-major)
//          alpha * A @ B^T  (TRANSB==1 : B is N x K row-major)
// Batched over blockIdx.z via element strides. CAUSAL==1 skips block tiles
// strictly above the diagonal (their outputs are never read).
#define BM 128
#define BN 128
#define BK 8
#define TM 8
#define TN 8

template<int TRANSB, int CAUSAL>
__global__ __launch_bounds__(256)
void sgemm_kernel(const float* __restrict__ A, const float* __restrict__ B,
                  float* __restrict__ C,
                  int M, int N, int K, int lda, int ldb, int ldc,
                  long strideA, long strideB, long strideC, float alpha)
{
    int row0 = blockIdx.y * BM;
    int col0 = blockIdx.x * BN;
    if (CAUSAL && col0 > row0 + (BM - 1)) return; // fully masked tile

    A += (long)blockIdx.z * strideA;
    B += (long)blockIdx.z * strideB;
    C += (long)blockIdx.z * strideC;

    __shared__ float As[BK][BM];
    __shared__ float Bs[BK][BN];

    int tid = threadIdx.x;
    int tx  = tid % 16;   // 16 x 16 thread grid
    int ty  = tid / 16;

    float acc[TM][TN];
#pragma unroll
    for (int i = 0; i < TM; i++)
#pragma unroll
        for (int j = 0; j < TN; j++) acc[i][j] = 0.f;

    // A-tile load mapping: 128 rows x 8 k, 4 elems/thread
    int aRow = tid >> 1;          // 0..127
    int aK0  = (tid & 1) * 4;     // 0 or 4

    // B-tile load mapping
    int bIdxA = tid >> 1;         // NT: n index 0..127
    int bK0   = (tid & 1) * 4;    // NT: k offset
    int bRowN = tid >> 5;         // NN: k index 0..7
    int bColN = (tid & 31) * 4;   // NN: n offset

    for (int k0 = 0; k0 < K; k0 += BK) {
#pragma unroll
        for (int i = 0; i < 4; i++) {
            int r = row0 + aRow, c = k0 + aK0 + i;
            As[aK0 + i][aRow] = (r < M && c < K) ? A[(long)r * lda + c] : 0.f;
        }
        if (TRANSB) {
#pragma unroll
            for (int i = 0; i < 4; i++) {
                int n = col0 + bIdxA, c = k0 + bK0 + i;
                Bs[bK0 + i][bIdxA] = (n < N && c < K) ? B[(long)n * ldb + c] : 0.f;
            }
        } else {
#pragma unroll
            for (int i = 0; i < 4; i++) {
                int r = k0 + bRowN, n = col0 + bColN + i;
                Bs[bRowN][bColN + i] = (r < K && n < N) ? B[(long)r * ldb + n] : 0.f;
            }
        }
        __syncthreads();

#pragma unroll
        for (int kk = 0; kk < BK; kk++) {
            float a[TM], b[TN];
#pragma unroll
            for (int i = 0; i < TM; i++) a[i] = As[kk][ty * TM + i];
#pragma unroll
            for (int j = 0; j < TN; j++) b[j] = Bs[kk][tx * TN + j];
#pragma unroll
            for (int i = 0; i < TM; i++)
#pragma unroll
                for (int j = 0; j < TN; j++) acc[i][j] += a[i] * b[j];
        }
        __syncthreads();
    }

#pragma unroll
    for (int i = 0; i < TM; i++) {
        int r = row0 + ty * TM + i;
        if (r >= M) continue;
#pragma unroll
        for (int j = 0; j < TN; j++) {
            int c = col0 + tx * TN + j;
            if (c < N) C[(long)r * ldc + c] = alpha * acc[i][j];
        }
    }
}

// ---------------- RMSNorm ----------------
__global__ void rmsnorm_kernel(const float* __restrict__ in,
                               const float* __restrict__ w,
                               float* __restrict__ out,
                               int L, int inStride, int outStride)
{
    int t = blockIdx.x;
    const float* x = in + (long)t * inStride;
    float*       y = out + (long)t * outStride;

    float ss = 0.f;
    for (int i = threadIdx.x; i < L; i += blockDim.x) {
        float v = x[i]; ss += v * v;
    }
    __shared__ float sh[33];
#pragma unroll
    for (int o = 16; o; o >>= 1) ss += __shfl_xor_sync(~0u, ss, o);
    int lane = threadIdx.x & 31, wrp = threadIdx.x >> 5;
    if (lane == 0) sh[wrp] = ss;
    __syncthreads();
    if (wrp == 0) {
        float v = (lane < (blockDim.x >> 5)) ? sh[lane] : 0.f;
#pragma unroll
        for (int o = 16; o; o >>= 1) v += __shfl_xor_sync(~0u, v, o);
        if (lane == 0) sh[32] = v;
    }
    __syncthreads();
    float r = rsqrtf(sh[32] / (float)L + EPS_RMS);
    for (int i = threadIdx.x; i < L; i += blockDim.x)
        y[i] = x[i] * r * w[i];
}

// ---------------- RoPE + repack into [h][t][...] layouts ----------------
__global__ void pack_rope_kernel(const int* __restrict__ positions,
                                 const float* __restrict__ q,      // [t][h*192+d]
                                 const float* __restrict__ kvbuf,  // [t][576]
                                 const float* __restrict__ kvup,   // [t][h*256+d]
                                 float* __restrict__ qfull,        // [h][t][192]
                                 float* __restrict__ kfull,        // [h][t][192]
                                 float* __restrict__ vbuf)         // [h][t][128]
{
    int t   = blockIdx.x;
    int tid = threadIdx.x; // 256
    float pos = (float)positions[t];

    __shared__ float kp[D_ROPE];
    if (tid < 32) {
        int i = tid;
        float inv = expf(-logf(10000.0f) * (2.0f * i) / (float)D_ROPE);
        float ang = pos * inv;
        float c = cosf(ang), s = sinf(ang);
        float x1 = kvbuf[(long)t * KVA_N + KV_LORA + 2 * i];
        float x2 = kvbuf[(long)t * KVA_N + KV_LORA + 2 * i + 1];
        kp[2 * i]     = x1 * c - x2 * s;
        kp[2 * i + 1] = x2 * c + x1 * s;
    }
    __syncthreads();

    // nope copies + broadcast roped k_pe
    for (int idx = tid; idx < NH * QK_HD; idx += blockDim.x) {
        int h = idx / QK_HD, d = idx % QK_HD;
        long dst = ((long)h * T_SEQ + t) * QK_HD + d;
        if (d < D_NOPE) {
            qfull[dst] = q   [(long)t * QB_N  + h * QK_HD + d];
            kfull[dst] = kvup[(long)t * KVB_N + h * (D_NOPE + D_V) + d];
        } else {
            kfull[dst] = kp[d - D_NOPE];
        }
    }
    // q_pe rope
    for (int idx = tid; idx < NH * (D_ROPE / 2); idx += blockDim.x) {
        int h = idx / (D_ROPE / 2), i = idx % (D_ROPE / 2);
        float inv = expf(-logf(10000.0f) * (2.0f * i) / (float)D_ROPE);
        float ang = pos * inv;
        float c = cosf(ang), s = sinf(ang);
        long src = (long)t * QB_N + h * QK_HD + D_NOPE;
        float x1 = q[src + 2 * i];
        float x2 = q[src + 2 * i + 1];
        long dst = ((long)h * T_SEQ + t) * QK_HD + D_NOPE;
        qfull[dst + 2 * i]     = x1 * c - x2 * s;
        qfull[dst + 2 * i + 1] = x2 * c + x1 * s;
    }
    // v pack
    for (int idx = tid; idx < NH * D_V; idx += blockDim.x) {
        int h = idx / D_V, d = idx % D_V;
        vbuf[((long)h * T_SEQ + t) * D_V + d] =
            kvup[(long)t * KVB_N + h * (D_NOPE + D_V) + D_NOPE + d];
    }
}

// ---------------- Causal softmax over scores rows ----------------
__global__ void softmax_causal_kernel(float* __restrict__ scores)
{
    int t = blockIdx.x, h = blockIdx.y;
    float* row = scores + ((long)h * T_SEQ + t) * T_SEQ;
    int n = t + 1;

    __shared__ float sh[33];
    int lane = threadIdx.x & 31, wrp = threadIdx.x >> 5;

    // max
    float m = -INFINITY;
    for (int i = threadIdx.x; i < n; i += blockDim.x) m = fmaxf(m, row[i]);
#pragma unroll
    for (int o = 16; o; o >>= 1) m = fmaxf(m, __shfl_xor_sync(~0u, m, o));
    if (lane == 0) sh[wrp] = m;
    __syncthreads();
    if (wrp == 0) {
        float v = (lane < (blockDim.x >> 5)) ? sh[lane] : -INFINITY;
#pragma unroll
        for (int o = 16; o; o >>= 1) v = fmaxf(v, __shfl_xor_sync(~0u, v, o));
        if (lane == 0) sh[32] = v;
    }
    __syncthreads();
    m = sh[32];
    __syncthreads();

    // exp + sum
    float s = 0.f;
    for (int i = threadIdx.x; i < n; i += blockDim.x) {
        float e = expf(row[i] - m);
        row[i] = e;
        s += e;
    }
#pragma unroll
    for (int o = 16; o; o >>= 1) s += __shfl_xor_sync(~0u, s, o);
    if (lane == 0) sh[wrp] = s;
    __syncthreads();
    if (wrp == 0) {
        float v = (lane < (blockDim.x >> 5)) ? sh[lane] : 0.f;
#pragma unroll
        for (int o = 16; o; o >>= 1) v += __shfl_xor_sync(~0u, v, o);
        if (lane == 0) sh[32] = v;
    }
    __syncthreads();
    float inv = 1.0f / sh[32];

    for (int i = threadIdx.x; i < n; i += blockDim.x) row[i] *= inv;
    // zero the masked tail so P @ V is a plain GEMM
    for (int i = n + threadIdx.x; i < T_SEQ; i += blockDim.x) row[i] = 0.f;
}

// ---------------- Launch ----------------
extern "C" void kernel_launch(void* const* d_in, const int* in_sizes, int n_in,
                              void* d_out, int out_size)
{
    const int*   positions = (const int*)  d_in[0];
    const float* hs        = (const float*)d_in[1];
    const float* w_qa      = (const float*)d_in[2];
    const float* qa_ln_w   = (const float*)d_in[3];
    const float* w_qb      = (const float*)d_in[4];
    const float* w_kva     = (const float*)d_in[5];
    const float* kva_ln_w  = (const float*)d_in[6];
    const float* w_kvb     = (const float*)d_in[7];
    const float* w_o       = (const float*)d_in[8];
    float* out = (float*)d_out;

    float *p_qa, *p_qc, *p_q, *p_kv, *p_kvc, *p_kvup, *p_qf, *p_kf, *p_v, *p_sc, *p_at;
    cudaGetSymbolAddress((void**)&p_qa,   g_qa);
    cudaGetSymbolAddress((void**)&p_qc,   g_qc);
    cudaGetSymbolAddress((void**)&p_q,    g_q);
    cudaGetSymbolAddress((void**)&p_kv,   g_kv);
    cudaGetSymbolAddress((void**)&p_kvc,  g_kvc);
    cudaGetSymbolAddress((void**)&p_kvup, g_kvup);
    cudaGetSymbolAddress((void**)&p_qf,   g_qfull);
    cudaGetSymbolAddress((void**)&p_kf,   g_kfull);
    cudaGetSymbolAddress((void**)&p_v,    g_v);
    cudaGetSymbolAddress((void**)&p_sc,   g_scores);
    cudaGetSymbolAddress((void**)&p_at,   g_attn);

    dim3 blk(256);
    auto cdiv = [](int a, int b) { return (a + b - 1) / b; };

    // G1: qa = hs @ w_qa  (2048 x 1536, K=5120)
    sgemm_kernel<0,0><<<dim3(cdiv(Q_LORA,BN), cdiv(T_SEQ,BM), 1), blk>>>(
        hs, w_qa, p_qa, T_SEQ, Q_LORA, HID, HID, Q_LORA, Q_LORA, 0, 0, 0, 1.f);

    // G2: kv = hs @ w_kva (2048 x 576, K=5120)
    sgemm_kernel<0,0><<<dim3(cdiv(KVA_N,BN), cdiv(T_SEQ,BM), 1), blk>>>(
        hs, w_kva, p_kv, T_SEQ, KVA_N, HID, HID, KVA_N, KVA_N, 0, 0, 0, 1.f);

    // RMSNorms
    rmsnorm_kernel<<<T_SEQ, 256>>>(p_qa, qa_ln_w, p_qc, Q_LORA, Q_LORA, Q_LORA);
    rmsnorm_kernel<<<T_SEQ, 256>>>(p_kv, kva_ln_w, p_kvc, KV_LORA, KVA_N, KV_LORA);

    // G3: q = qc @ w_qb (2048 x 3072, K=1536)
    sgemm_kernel<0,0><<<dim3(cdiv(QB_N,BN), cdiv(T_SEQ,BM), 1), blk>>>(
        p_qc, w_qb, p_q, T_SEQ, QB_N, Q_LORA, Q_LORA, QB_N, QB_N, 0, 0, 0, 1.f);

    // G4: kvup = kvc @ w_kvb (2048 x 4096, K=512)
    sgemm_kernel<0,0><<<dim3(cdiv(KVB_N,BN), cdiv(T_SEQ,BM), 1), blk>>>(
        p_kvc, w_kvb, p_kvup, T_SEQ, KVB_N, KV_LORA, KV_LORA, KVB_N, KVB_N, 0, 0, 0, 1.f);

    // RoPE + repack
    pack_rope_kernel<<<T_SEQ, 256>>>(positions, p_q, p_kv, p_kvup, p_qf, p_kf, p_v);

    // G5: scores[h] = SCALE * qfull[h] @ kfull[h]^T  (causal tile skip)
    sgemm_kernel<1,1><<<dim3(cdiv(T_SEQ,BN), cdiv(T_SEQ,BM), NH), blk>>>(
        p_qf, p_kf, p_sc, T_SEQ, T_SEQ, QK_HD, QK_HD, QK_HD, T_SEQ,
        (long)T_SEQ * QK_HD, (long)T_SEQ * QK_HD, (long)T_SEQ * T_SEQ, SCALE);

    // softmax rows (zero masked tail)
    softmax_causal_kernel<<<dim3(T_SEQ, NH), 256>>>(p_sc);

    // G6: attn[t][h*128+d] = P[h] @ V[h]
    sgemm_kernel<0,0><<<dim3(cdiv(D_V,BN), cdiv(T_SEQ,BM), NH), blk>>>(
        p_sc, p_v, p_at, T_SEQ, D_V, T_SEQ, T_SEQ, D_V, O_K,
        (long)T_SEQ * T_SEQ, (long)T_SEQ * D_V, (long)D_V, 1.f);

    // G7: out = attn @ w_o (2048 x 5120, K=2048)
    sgemm_kernel<0,0><<<dim3(cdiv(HID,BN), cdiv(T_SEQ,BM), 1), blk>>>(
        p_at, w_o, out, T_SEQ, HID, O_K, O_K, HID, HID, 0, 0, 0, 1.f);
}